// round 17
// baseline (speedup 1.0000x reference)
#include <cuda_runtime.h>
#include <cuda_fp16.h>
#include <cstdint>
#include <math.h>

#define BB 32
#define SS 196
#define TT 64
#define HH 1024
#define VV 32000
#define RR 4096
#define NB 148

// k_recur smem byte offsets (f16 gate stages: 2 x 8KB per operand)
#define OFF_W    128
#define OFF_X    (128 + 16384)
#define OFF_GATE (128 + 32768)
#define OFF_P2S  (OFF_GATE + 4096)
#define SMEM_RECUR (OFF_P2S + 6144)

// tf32 pgemm smem (M2/E)
#define SMEM_WK (128 + 3*32768)
// f16 logits smem
#define SMEM_LF (128 + 3*16384)

// ---------------- scratch ----------------
__device__ __half g_M2h[(size_t)BB*SS*HH];     // memory @ attn_W, f16
__device__ __half g_memh[(size_t)BB*SS*HH];    // memory, f16 copy (for ctx)
__device__ float  g_ET [(size_t)TT*RR*BB];
__device__ __half g_Wfh[(size_t)128*16*4096];  // f16 gate weight fragments
__device__ __half g_xfh[(size_t)24*4096];      // f16 x fragments
__device__ __half g_Af [(size_t)16*131072];    // logits A f16 fragments
__device__ __half g_Wo [(size_t)32000*1024];   // logits B f16 fragments
__device__ float  g_AM2[(size_t)49*131072];
__device__ float  g_BM2[(size_t)8*131072];
__device__ float  g_AE [(size_t)16*131072];
__device__ float  g_BE [(size_t)32*131072];
__device__ float  g_h [BB*HH];
__device__ float  g_c [BB*HH];
__device__ float  g_scores[BB*SS];
__device__ unsigned g_bar;
__device__ unsigned g_p2done;

// ---------------- helpers ----------------
__device__ __forceinline__ float f2tf32(float x) {
    uint32_t u; asm("cvt.rna.tf32.f32 %0, %1;" : "=r"(u) : "f"(x));
    return __uint_as_float(u);
}
__device__ __forceinline__ void mma_op(float* c, const uint32_t* a, const uint32_t* b) {
    asm volatile(
        "mma.sync.aligned.m16n8k8.row.col.f32.tf32.tf32.f32 "
        "{%0,%1,%2,%3},{%4,%5,%6,%7},{%8,%9},{%0,%1,%2,%3};"
        : "+f"(c[0]), "+f"(c[1]), "+f"(c[2]), "+f"(c[3])
        : "r"(a[0]), "r"(a[1]), "r"(a[2]), "r"(a[3]), "r"(b[0]), "r"(b[1]));
}
__device__ __forceinline__ void mma_f16(float* c, const uint4& a, const uint2& b) {
    asm volatile(
        "mma.sync.aligned.m16n8k16.row.col.f32.f16.f16.f32 "
        "{%0,%1,%2,%3},{%4,%5,%6,%7},{%8,%9},{%0,%1,%2,%3};"
        : "+f"(c[0]), "+f"(c[1]), "+f"(c[2]), "+f"(c[3])
        : "r"(a.x), "r"(a.y), "r"(a.z), "r"(a.w), "r"(b.x), "r"(b.y));
}
__device__ __forceinline__ uint32_t smem_u32(const void* p) {
    uint32_t a;
    asm("{ .reg .u64 t; cvta.to.shared.u64 t, %1; cvt.u32.u64 %0, t; }" : "=r"(a) : "l"(p));
    return a;
}
__device__ __forceinline__ size_t xf_off_h(int k, int n, int parity) {
    int cc = k >> 7;
    int ccp = (cc < 8) ? cc : (cc + parity * 8);
    int c16 = (k >> 4) & 7;
    int nt = n >> 3;
    int kk = k & 15;
    int lane = ((n & 7) << 2) | ((kk >> 1) & 3);
    int hidx = ((kk >> 3) << 1) | (kk & 1);
    return ((((size_t)(ccp * 8 + c16) * 4 + nt) * 32 + lane) * 4) + hidx;
}

#define MB_WAIT(mbar, par) do { uint32_t _d; \
    do { asm volatile("{\n\t.reg .pred p;\n\t" \
        "mbarrier.try_wait.parity.acquire.cta.shared::cta.b64 p, [%1], %2;\n\t" \
        "selp.b32 %0, 1, 0, p;\n\t}" \
        : "=r"(_d) : "r"(mbar), "r"((uint32_t)(par)) : "memory"); } while (!_d); } while (0)

#define BULK_CPN(dst, src, bytes, mb) \
    asm volatile("cp.async.bulk.shared::cta.global.mbarrier::complete_tx::bytes " \
                 "[%0], [%1], %2, [%3];" \
                 :: "r"(dst), "l"(src), "r"((uint32_t)(bytes)), "r"(mb) : "memory")

// ---------------- tf32 fragment packs (prologue) ----------------
__global__ __launch_bounds__(256) void k_packA(
    const float* __restrict__ src, const int* __restrict__ gidx,
    const float* __restrict__ gtab, float* __restrict__ dst)
{
    int idx = blockIdx.x * 256 + threadIdx.x;
    int lane = idx & 31, mtile = (idx >> 5) & 7, c8 = (idx >> 8) & 127, mblk = idx >> 15;
    int m0 = mblk * 128 + mtile * 16 + (lane >> 2);
    int k0 = c8 * 8 + (lane & 3);
    const float* r0 = gidx ? (gtab + (size_t)gidx[m0    ] * HH) : (src + (size_t)m0       * HH);
    const float* r1 = gidx ? (gtab + (size_t)gidx[m0 + 8] * HH) : (src + (size_t)(m0 + 8) * HH);
    float4 v;
    v.x = f2tf32(r0[k0]);     v.y = f2tf32(r1[k0]);
    v.z = f2tf32(r0[k0 + 4]); v.w = f2tf32(r1[k0 + 4]);
    ((float4*)dst)[idx] = v;
}

__global__ __launch_bounds__(256) void k_packB(
    const float* __restrict__ src, float* __restrict__ dst, int ldb, int trans)
{
    size_t idx = (size_t)blockIdx.x * 256 + threadIdx.x;
    int lane = (int)(idx & 31);
    int nt   = (int)((idx >> 5) & 15);
    int c8   = (int)((idx >> 9) & 127);
    int nblk = (int)(idx >> 16);
    int n = nblk * 128 + nt * 8 + (lane >> 2);
    int k = c8 * 8 + (lane & 3);
    float2 v;
    if (trans) {
        v.x = f2tf32(src[(size_t)k * ldb + n]);
        v.y = f2tf32(src[(size_t)(k + 4) * ldb + n]);
    } else {
        v.x = f2tf32(src[(size_t)n * ldb + k]);
        v.y = f2tf32(src[(size_t)n * ldb + k + 4]);
    }
    ((float2*)dst)[idx] = v;
}

// ---------------- f16 gate weight fragment pack ----------------
__global__ __launch_bounds__(256) void k_packWFH(
    const float* __restrict__ W_ih, const float* __restrict__ W_hh)
{
    int idx = blockIdx.x * 256 + threadIdx.x;
    int lane = idx & 31;
    int mt   = (idx >> 5) & 1;
    int c16  = (idx >> 6) & 7;
    int cc   = (idx >> 9) & 15;
    int blk  = idx >> 13;
    int grp = lane >> 2, tg = lane & 3;
    int m = mt * 16 + grp;
    int kbase = cc * 128 + c16 * 16 + tg * 2;

    auto wval = [&](int mm, int kk) -> float {
        int g = mm >> 3, jo = mm & 7;
        int r = g * 1024 + blk * 8 + jo;
        return (kk < 1024) ? W_ih[(size_t)r * 2048 + 1024 + kk]
                           : W_hh[(size_t)r * 1024 + (kk - 1024)];
    };
    __half2 h0 = __floats2half2_rn(wval(m,     kbase),     wval(m,     kbase + 1));
    __half2 h1 = __floats2half2_rn(wval(m + 8, kbase),     wval(m + 8, kbase + 1));
    __half2 h2 = __floats2half2_rn(wval(m,     kbase + 8), wval(m,     kbase + 9));
    __half2 h3 = __floats2half2_rn(wval(m + 8, kbase + 8), wval(m + 8, kbase + 9));
    uint4 v;
    v.x = *(uint32_t*)&h0; v.y = *(uint32_t*)&h1;
    v.z = *(uint32_t*)&h2; v.w = *(uint32_t*)&h3;
    ((uint4*)g_Wfh)[idx] = v;
}

// ---------------- W_out f16 B-fragment pack ----------------
__global__ __launch_bounds__(256) void k_packWoH(const float* __restrict__ W_out)
{
    size_t idx = (size_t)blockIdx.x * 256 + threadIdx.x;
    int lane  = (int)(idx & 31);
    int ntile = (int)((idx >> 5) & 15);
    int c16   = (int)((idx >> 9) & 63);
    int nblk  = (int)(idx >> 15);
    int grp = lane >> 2, tg = lane & 3;
    int n = nblk * 128 + ntile * 8 + grp;
    int k = c16 * 16 + tg * 2;
    const float* src = W_out + (size_t)n * HH + k;
    __half2 lo = __floats2half2_rn(src[0], src[1]);
    __half2 hi = __floats2half2_rn(src[8], src[9]);
    ((__half2*)g_Wo)[idx * 2]     = lo;
    ((__half2*)g_Wo)[idx * 2 + 1] = hi;
}

// ---------------- memory -> f16 copy ----------------
__global__ __launch_bounds__(256) void k_packMemH(const float* __restrict__ src)
{
    int i = blockIdx.x * 256 + threadIdx.x;    // uint4 id (8 halves); 802816 total
    float4 a = ((const float4*)src)[(size_t)i * 2];
    float4 b = ((const float4*)src)[(size_t)i * 2 + 1];
    __half2 h0 = __floats2half2_rn(a.x, a.y), h1 = __floats2half2_rn(a.z, a.w);
    __half2 h2 = __floats2half2_rn(b.x, b.y), h3 = __floats2half2_rn(b.z, b.w);
    uint4 v;
    v.x = *(uint32_t*)&h0; v.y = *(uint32_t*)&h1;
    v.z = *(uint32_t*)&h2; v.w = *(uint32_t*)&h3;
    ((uint4*)g_memh)[i] = v;
}

// ---------------- no-CCTL global barrier ----------------
__device__ __forceinline__ void gridbar(unsigned target) {
    __syncthreads();
    if (threadIdx.x == 0) {
        unsigned one = 1u, x;
        asm volatile("red.release.gpu.global.add.u32 [%0], %1;"
                     :: "l"(&g_bar), "r"(one) : "memory");
        do {
            asm volatile("ld.acquire.gpu.global.u32 %0, [%1];"
                         : "=r"(x) : "l"(&g_bar));
        } while (x < target);
    }
    __syncthreads();
}

// ---------------- persistent recurrence ----------------
__global__ __launch_bounds__(1024, 1) void k_recur(
    const float* __restrict__ b_ih, const float* __restrict__ b_hh)
{
    extern __shared__ char smem[];
    float* gate_s = (float*)(smem + OFF_GATE);
    float* p2s    = (float*)(smem + OFF_P2S);
    const uint32_t sbase = smem_u32(smem);
    const uint32_t mb0 = sbase, mb1 = sbase + 8;

    const int tid = threadIdx.x, bid = blockIdx.x;
    const int w = tid >> 5, lane = tid & 31;
    const bool gateblk = (bid < 128);

    if (tid == 0) {
        asm volatile("mbarrier.init.shared.b64 [%0], %1;" :: "r"(mb0), "r"(1u) : "memory");
        asm volatile("mbarrier.init.shared.b64 [%0], %1;" :: "r"(mb1), "r"(1u) : "memory");
    }
    __syncthreads();

    unsigned tgt = NB;

    for (int t = 0; t < TT; t++) {
        const int par = t & 1;

        auto issue = [&](int cc, int slot) {
            uint32_t mb = (slot & 1) ? mb1 : mb0;
            uint32_t wd = sbase + OFF_W + (slot & 1) * 8192;
            uint32_t xd = sbase + OFF_X + (slot & 1) * 8192;
            const __half* ws = g_Wfh + ((size_t)bid * 16 + cc) * 4096;
            int ccp = (cc < 8) ? cc : (cc + par * 8);
            const __half* xs = g_xfh + (size_t)ccp * 4096;
            asm volatile("mbarrier.arrive.expect_tx.shared.b64 _, [%0], %1;"
                         :: "r"(mb), "r"(16384u) : "memory");
            BULK_CPN(wd, ws, 8192u, mb);
            BULK_CPN(xd, xs, 8192u, mb);
        };

        if (gateblk && tid == 0) { issue(8, 0); issue(9, 1); }

        // ======== P1: scores (f16 M2) ========
        for (int p = bid * 32 + w; p < BB * SS; p += NB * 32) {
            int b = p / SS;
            const uint4* m4 = (const uint4*)(g_M2h + (size_t)p * HH);
            const float4* h4 = (const float4*)(g_h + b * HH);
            float a = 0.f;
            #pragma unroll
            for (int i = 0; i < 4; i++) {
                uint4 mv = m4[i * 32 + lane];
                float4 hv0 = __ldcg(&h4[(i * 32 + lane) * 2]);
                float4 hv1 = __ldcg(&h4[(i * 32 + lane) * 2 + 1]);
                __half2* hp = (__half2*)&mv;
                float2 f;
                f = __half22float2(hp[0]); a += f.x * hv0.x + f.y * hv0.y;
                f = __half22float2(hp[1]); a += f.x * hv0.z + f.y * hv0.w;
                f = __half22float2(hp[2]); a += f.x * hv1.x + f.y * hv1.y;
                f = __half22float2(hp[3]); a += f.x * hv1.z + f.y * hv1.w;
            }
            #pragma unroll
            for (int o = 16; o; o >>= 1) a += __shfl_xor_sync(0xffffffffu, a, o);
            if (!lane) g_scores[p] = a;
        }
        gridbar(tgt); tgt += NB;

        // ======== P2: softmax + ctx (f16 memory) -> f16 x fragments ========
        if (gateblk) {
            float* red  = p2s;
            float* swp  = p2s + 256;
            float* part = p2s + 512;
            int b = bid >> 2, jblk = bid & 3;
            float v = -1e30f;
            if (tid < 256) {
                v = (tid < SS) ? __ldcg(&g_scores[b * SS + tid]) : -1e30f;
                red[tid] = v;
            }
            __syncthreads();
            for (int o = 128; o; o >>= 1) { if (tid < o) red[tid] = fmaxf(red[tid], red[tid+o]); __syncthreads(); }
            float mx = red[0]; __syncthreads();
            float e = 0.f;
            if (tid < 256) { e = (tid < SS) ? expf(v - mx) : 0.f; red[tid] = e; }
            __syncthreads();
            for (int o = 128; o; o >>= 1) { if (tid < o) red[tid] += red[tid+o]; __syncthreads(); }
            float inv = 1.f / red[0];
            if (tid < 256) swp[tid] = e * inv;
            __syncthreads();

            int jj = tid & 255, sp = tid >> 8;
            int j = jblk * 256 + jj;
            const __half* mp = g_memh + ((size_t)b * SS + sp * 49) * HH + j;
            float acc2 = 0.f;
            #pragma unroll 7
            for (int s = 0; s < 49; s++)
                acc2 += swp[sp * 49 + s] * __half2float(__ldg(mp + (size_t)s * HH));
            part[sp * 256 + jj] = acc2;
            __syncthreads();
            if (tid < 256) {
                float cv = part[jj] + part[256+jj] + part[512+jj] + part[768+jj];
                g_xfh[xf_off_h(j, b, 0)] = __float2half_rn(cv);
            }
            __syncthreads();
            if (tid == 0) {
                unsigned one = 1u;
                asm volatile("red.release.gpu.global.add.u32 [%0], %1;"
                             :: "l"(&g_p2done), "r"(one) : "memory");
            }
        }

        // ======== P3: f16 gates pipeline (h-first) + cell ========
        if (gateblk) {
            if (tid < 256) {
                const int w8 = tid >> 5;
                const int mt = w8 & 1, nt = w8 >> 1;
                const int grp = lane >> 2, tg = lane & 3;
                float acc[4] = {0.f, 0.f, 0.f, 0.f};

                #pragma unroll
                for (int i = 0; i < 16; i++) {
                    uint32_t mb = (i & 1) ? mb1 : mb0;
                    MB_WAIT(mb, (i >> 1) & 1);
                    const uint4* wb = (const uint4*)(smem + OFF_W + (i & 1) * 8192);
                    const uint2* xb = (const uint2*)(smem + OFF_X + (i & 1) * 8192);
                    #pragma unroll
                    for (int c16 = 0; c16 < 8; c16++) {
                        uint4 a4 = wb[(c16 * 2 + mt) * 32 + lane];
                        uint2 b2 = xb[(c16 * 4 + nt) * 32 + lane];
                        mma_f16(acc, a4, b2);
                    }
                    asm volatile("bar.sync 7, 256;" ::: "memory");
                    if (tid == 0 && i < 14) {
                        int nxt = (i + 2 + 8) & 15;
                        if (i == 6) {
                            unsigned x, want = 128u * (unsigned)(t + 1);
                            do {
                                asm volatile("ld.acquire.gpu.global.u32 %0, [%1];"
                                             : "=r"(x) : "l"(&g_p2done));
                            } while (x < want);
                        }
                        issue(nxt, i + 2);
                    }
                }

                *(float2*)&gate_s[(mt*16 + grp    ) * 32 + nt*8 + tg*2] = make_float2(acc[0], acc[1]);
                *(float2*)&gate_s[(mt*16 + grp + 8) * 32 + nt*8 + tg*2] = make_float2(acc[2], acc[3]);
            }
            __syncthreads();
            if (tid < 256) {
                int b = tid & 31, jo = tid >> 5;
                int j = bid * 8 + jo;
                float pre[4];
                #pragma unroll
                for (int g = 0; g < 4; g++) {
                    pre[g] = gate_s[(g*8 + jo) * 32 + b]
                           + __ldg(&g_ET[((size_t)t * RR + g*1024 + j) * 32 + b])
                           + __ldg(&b_ih[g*1024 + j]) + __ldg(&b_hh[g*1024 + j]);
                }
                float ig = 1.f / (1.f + expf(-pre[0]));
                float fg = 1.f / (1.f + expf(-pre[1]));
                float gg = tanhf(pre[2]);
                float og = 1.f / (1.f + expf(-pre[3]));
                int idx = b * HH + j;
                float cn = fg * g_c[idx] + ig * gg;
                float hn = og * tanhf(cn);
                g_c[idx] = cn;
                g_h[idx] = hn;
                g_xfh[xf_off_h(1024 + j, b, (t + 1) & 1)] = __float2half_rn(hn);
                int m = t * 32 + b;
                int mblk = m >> 7, c16 = j >> 4, mtile = (m >> 4) & 7;
                int q   = ((m >> 3) & 1) + 2 * ((j >> 3) & 1);
                int lnA = ((m & 7) << 2) | ((j >> 1) & 3);
                size_t off = (((((size_t)mblk * 64 + c16) * 8 + mtile) * 32 + lnA) * 8)
                           + (size_t)(q * 2 + (j & 1));
                g_Af[off] = __float2half_rn(hn);
            }
        }
        gridbar(tgt); tgt += NB;
    }
}

// ---------------- f16 pipelined logits GEMM ----------------
__global__ __launch_bounds__(256, 2) void k_logits(
    const float* __restrict__ bias, float* __restrict__ out)
{
    extern __shared__ char smem[];
    const uint32_t sbase = smem_u32(smem);
    const int tid = threadIdx.x;
    const int mblk = blockIdx.x, nblk = blockIdx.y;
    const int warp = tid >> 5, lane = tid & 31;
    const int wm = warp >> 1, wn = warp & 1;
    const int grp = lane >> 2, tg = lane & 3;

    if (tid == 0) {
        #pragma unroll
        for (int i = 0; i < 3; i++)
            asm volatile("mbarrier.init.shared.b64 [%0], %1;"
                         :: "r"(sbase + i * 8), "r"(1u) : "memory");
    }
    __syncthreads();

    float acc[2][8][4] = {};

    auto issue = [&](int s) {
        int buf = s % 3;
        uint32_t mb = sbase + buf * 8;
        uint32_t ad = sbase + 128 + buf * 16384;
        uint32_t bd = ad + 8192;
        const __half* as = g_Af + ((size_t)mblk * 64 + s * 2) * 2048;
        const __half* bs = g_Wo + ((size_t)nblk * 64 + s * 2) * 2048;
        asm volatile("mbarrier.arrive.expect_tx.shared.b64 _, [%0], %1;"
                     :: "r"(mb), "r"(16384u) : "memory");
        BULK_CPN(ad, as, 8192u, mb);
        BULK_CPN(bd, bs, 8192u, mb);
    };

    if (tid == 0) { issue(0); issue(1); }

    for (int s = 0; s < 32; s++) {
        int buf = s % 3;
        MB_WAIT(sbase + buf * 8, (s / 3) & 1);
        const uint4* Ab = (const uint4*)(smem + 128 + buf * 16384);
        const uint2* Bb = (const uint2*)(smem + 128 + buf * 16384 + 8192);
        #pragma unroll
        for (int cl = 0; cl < 2; cl++) {
            uint4 a0 = Ab[(cl * 8 + wm * 2 + 0) * 32 + lane];
            uint4 a1 = Ab[(cl * 8 + wm * 2 + 1) * 32 + lane];
            #pragma unroll
            for (int nt = 0; nt < 8; nt++) {
                uint2 b2 = Bb[(cl * 16 + wn * 8 + nt) * 32 + lane];
                mma_f16(acc[0][nt], a0, b2);
                mma_f16(acc[1][nt], a1, b2);
            }
        }
        __syncthreads();
        if (tid == 0 && s + 2 < 32) issue(s + 2);
    }

    #pragma unroll
    for (int mt = 0; mt < 2; mt++) {
        int m0 = mblk * 128 + (wm * 2 + mt) * 16 + grp;
        int m2 = m0 + 8;
        #pragma unroll
        for (int nt = 0; nt < 8; nt++) {
            int ng = nblk * 128 + wn * 64 + nt * 8 + tg * 2;
            float* a4 = acc[mt][nt];
            float b0 = __ldg(bias + ng), b1 = __ldg(bias + ng + 1);
            size_t r1 = ((size_t)(m0 & 31) * TT + (m0 >> 5)) * VV;
            size_t r2 = ((size_t)(m2 & 31) * TT + (m2 >> 5)) * VV;
            *(float2*)(out + r1 + ng) = make_float2(a4[0] + b0, a4[1] + b1);
            *(float2*)(out + r2 + ng) = make_float2(a4[2] + b0, a4[3] + b1);
        }
    }
}

// ---------------- tf32 pipelined GEMM (prologue; mode 3 = half row-major out) ----------------
__global__ __launch_bounds__(256, 2) void k_pgemm(
    const float* __restrict__ Afrag, const float* __restrict__ Bfrag,
    float* __restrict__ C, int Nn, int mode)
{
    extern __shared__ char smem[];
    const uint32_t sbase = smem_u32(smem);
    const int tid = threadIdx.x;
    const int mblk = blockIdx.x, nblk = blockIdx.y;
    const int warp = tid >> 5, lane = tid & 31;
    const int wm = warp >> 1, wn = warp & 1;
    const int grp = lane >> 2, tg = lane & 3;

    if (tid == 0) {
        #pragma unroll
        for (int i = 0; i < 3; i++)
            asm volatile("mbarrier.init.shared.b64 [%0], %1;"
                         :: "r"(sbase + i * 8), "r"(1u) : "memory");
    }
    __syncthreads();

    float acc[2][8][4] = {};

    auto issue = [&](int s) {
        int buf = s % 3;
        uint32_t mb = sbase + buf * 8;
        uint32_t ad = sbase + 128 + buf * 32768;
        uint32_t bd = ad + 16384;
        const float* as = Afrag + ((size_t)mblk * 128 + s * 4) * 1024;
        const float* bs = Bfrag + ((size_t)nblk * 128 + s * 4) * 1024;
        asm volatile("mbarrier.arrive.expect_tx.shared.b64 _, [%0], %1;"
                     :: "r"(mb), "r"(32768u) : "memory");
        BULK_CPN(ad, as, 16384u, mb);
        BULK_CPN(bd, bs, 16384u, mb);
    };

    if (tid == 0) { issue(0); issue(1); }

    for (int s = 0; s < 32; s++) {
        int buf = s % 3;
        MB_WAIT(sbase + buf * 8, (s / 3) & 1);
        const float4* Ab = (const float4*)(smem + 128 + buf * 32768);
        const float2* Bb = (const float2*)(smem + 128 + buf * 32768 + 16384);
        #pragma unroll
        for (int c8 = 0; c8 < 4; c8++) {
            float4 a0 = Ab[(c8 * 8 + wm * 2 + 0) * 32 + lane];
            float4 a1 = Ab[(c8 * 8 + wm * 2 + 1) * 32 + lane];
            #pragma unroll
            for (int nt = 0; nt < 8; nt++) {
                float2 b2 = Bb[(c8 * 16 + wn * 8 + nt) * 32 + lane];
                mma_op(acc[0][nt], (const uint32_t*)&a0, (const uint32_t*)&b2);
                mma_op(acc[1][nt], (const uint32_t*)&a1, (const uint32_t*)&b2);
            }
        }
        __syncthreads();
        if (tid == 0 && s + 2 < 32) issue(s + 2);
    }

    #pragma unroll
    for (int mt = 0; mt < 2; mt++) {
        int m0 = mblk * 128 + (wm * 2 + mt) * 16 + grp;
        int m2 = m0 + 8;
        #pragma unroll
        for (int nt = 0; nt < 8; nt++) {
            int ng = nblk * 128 + wn * 64 + nt * 8 + tg * 2;
            float* a4 = acc[mt][nt];
            if (mode == 2) {
                int b1i = m0 >> 6, t1 = m0 & 63;
                int b2i = m2 >> 6, t2 = m2 & 63;
                size_t p1 = ((size_t)t1 * RR + ng) * 32 + b1i;
                size_t p2 = ((size_t)t2 * RR + ng) * 32 + b2i;
                C[p1] = a4[0]; C[p1 + 32] = a4[1];
                C[p2] = a4[2]; C[p2 + 32] = a4[3];
            } else if (mode == 3) {
                __half* Ch = (__half*)C;
                *(__half2*)(Ch + (size_t)m0 * Nn + ng) = __floats2half2_rn(a4[0], a4[1]);
                *(__half2*)(Ch + (size_t)m2 * Nn + ng) = __floats2half2_rn(a4[2], a4[3]);
            } else {
                *(float2*)(C + (size_t)m0 * Nn + ng) = make_float2(a4[0], a4[1]);
                *(float2*)(C + (size_t)m2 * Nn + ng) = make_float2(a4[2], a4[3]);
            }
        }
    }
}

// ---------------- small kernels ----------------
__global__ void k_zero() {
    int i = blockIdx.x * 1024 + threadIdx.x;
    g_h[i] = 0.f; g_c[i] = 0.f;
    uint32_t* xw = (uint32_t*)g_xfh;
    for (int j = i; j < 49152; j += 32768) xw[j] = 0u;
    if (i == 0) { g_bar = 0u; g_p2done = 0u; }
}

__global__ void k_copy_hc(float* __restrict__ out) {
    int i = blockIdx.x * 512 + threadIdx.x;
    const size_t OFF = (size_t)BB * TT * VV;
    out[OFF + i] = g_h[i];
    out[OFF + (size_t)BB*HH + i] = g_c[i];
}

// ---------------- launch ----------------
extern "C" void kernel_launch(void* const* d_in, const int* in_sizes, int n_in,
                              void* d_out, int out_size)
{
    const float* memory  = (const float*)d_in[0];
    const int*   captions= (const int*  )d_in[1];
    const float* emb     = (const float*)d_in[2];
    const float* attn_W  = (const float*)d_in[3];
    const float* W_ih    = (const float*)d_in[4];
    const float* W_hh    = (const float*)d_in[5];
    const float* b_ih    = (const float*)d_in[6];
    const float* b_hh    = (const float*)d_in[7];
    const float* W_out   = (const float*)d_in[8];
    const float* b_out   = (const float*)d_in[9];
    float* out = (float*)d_out;

    static float *pM2h = nullptr, *pET = nullptr,
                 *pAM2 = nullptr, *pBM2 = nullptr, *pAE = nullptr, *pBE = nullptr;
    if (!pM2h) {
        cudaGetSymbolAddress((void**)&pM2h, g_M2h);
        cudaGetSymbolAddress((void**)&pET,  g_ET);
        cudaGetSymbolAddress((void**)&pAM2, g_AM2);
        cudaGetSymbolAddress((void**)&pBM2, g_BM2);
        cudaGetSymbolAddress((void**)&pAE,  g_AE);
        cudaGetSymbolAddress((void**)&pBE,  g_BE);
        cudaFuncSetAttribute(k_recur,  cudaFuncAttributeMaxDynamicSharedMemorySize, SMEM_RECUR);
        cudaFuncSetAttribute(k_pgemm,  cudaFuncAttributeMaxDynamicSharedMemorySize, SMEM_WK);
        cudaFuncSetAttribute(k_logits, cudaFuncAttributeMaxDynamicSharedMemorySize, SMEM_LF);
    }

    k_zero<<<32, 1024>>>();

    // fragment packs + f16 memory copy
    k_packA<<<6272, 256>>>(memory, nullptr, nullptr, pAM2);
    k_packB<<<2048, 256>>>(attn_W, pBM2, HH, 1);
    k_packA<<<2048, 256>>>(nullptr, captions, emb, pAE);
    k_packB<<<8192, 256>>>(W_ih, pBE, 2048, 0);
    k_packWFH<<<4096, 256>>>(W_ih, W_hh);
    k_packWoH<<<32000, 256>>>(W_out);
    k_packMemH<<<3136, 256>>>(memory);

    // prologue GEMMs (M2 -> f16, E -> fp32 transposed)
    k_pgemm<<<dim3(49, 8), 256, SMEM_WK>>>(pAM2, pBM2, pM2h, HH, 3);
    k_pgemm<<<dim3(16, 32), 256, SMEM_WK>>>(pAE, pBE, pET, RR, 2);

    // recurrence
    k_recur<<<NB, 1024, SMEM_RECUR>>>(b_ih, b_hh);

    // f16 logits
    k_logits<<<dim3(16, 250), 256, SMEM_LF>>>(b_out, out);

    k_copy_hc<<<64, 512>>>(out);
}